// round 4
// baseline (speedup 1.0000x reference)
#include <cuda_runtime.h>

#define BB 512
#define KK 800
#define DD 512
#define LL 500000
#define NB 32
#define BSZ (LL / NB)          // 15625 rows per bucket, exact

// Scratch: per-b bucketed items packed as (idx << 10) | k  (idx<2^19, k<2^10)
__device__ unsigned int g_items[(size_t)BB * KK];
// Per-(b,bucket) start offsets; g_off[b][NB] = KK sentinel.
__device__ int g_off[BB * (NB + 1)];

// ---------------------------------------------------------------------------
// Kernel 1: per-b counting sort into NB idx-range buckets.
// ---------------------------------------------------------------------------
__global__ __launch_bounds__(256) void bucket_kernel(const int* __restrict__ shortlist)
{
    __shared__ int hist[NB];
    __shared__ int cursor[NB];
    __shared__ unsigned int s_items[KK];

    const int b = blockIdx.x;
    const int t = threadIdx.x;

    if (t < NB) hist[t] = 0;
    __syncthreads();

    for (int i = t; i < KK; i += 256) {
        unsigned idx = (unsigned)shortlist[b * KK + i];
        s_items[i] = (idx << 10) | (unsigned)i;
        atomicAdd(&hist[idx / BSZ], 1);
    }
    __syncthreads();

    if (t < 32) {
        int h = hist[t];
        int v = h;
        #pragma unroll
        for (int o = 1; o < 32; o <<= 1) {
            int n = __shfl_up_sync(0xffffffffu, v, o);
            if (t >= o) v += n;
        }
        int excl = v - h;
        cursor[t] = excl;
        g_off[b * (NB + 1) + t] = excl;
        if (t == 31) g_off[b * (NB + 1) + NB] = KK;
    }
    __syncthreads();

    for (int i = t; i < KK; i += 256) {
        unsigned it = s_items[i];
        int bucket = (int)((it >> 10) / BSZ);
        int pos = atomicAdd(&cursor[bucket], 1);
        g_items[(size_t)b * KK + pos] = it;
    }
}

// ---------------------------------------------------------------------------
// Kernel 2: dot products, grid = (b fast, bucket slow).
// 2 items per warp iteration -> 8 outstanding LDG.128 per warp.
// ---------------------------------------------------------------------------
__global__ __launch_bounds__(256, 5) void dot_kernel(
    const float* __restrict__ embed,
    const float* __restrict__ sp_weight,
    const float* __restrict__ sp_bias,
    float*       __restrict__ out)
{
    __shared__ float4 s_embed[DD / 4];

    const int b      = blockIdx.x;
    const int bucket = blockIdx.y;

    const int begin = g_off[b * (NB + 1) + bucket];
    const int end   = g_off[b * (NB + 1) + bucket + 1];
    if (begin == end) return;                  // empty bucket: skip staging

    const float4* erow = reinterpret_cast<const float4*>(embed + (size_t)b * DD);
    for (int i = threadIdx.x; i < DD / 4; i += blockDim.x)
        s_embed[i] = erow[i];
    __syncthreads();

    const int warp = threadIdx.x >> 5;
    const int lane = threadIdx.x & 31;

    const unsigned int* items = g_items + (size_t)b * KK;

    for (int j0 = begin + warp * 2; j0 < end; j0 += 16) {
        const unsigned itA = items[j0];
        const bool has2 = (j0 + 1) < end;
        const unsigned itB = items[has2 ? (j0 + 1) : j0];

        const int       kA   = (int)(itA & 1023u);
        const long long idxA = (long long)(itA >> 10);
        const int       kB   = (int)(itB & 1023u);
        const long long idxB = (long long)(itB >> 10);

        const float4* wA = reinterpret_cast<const float4*>(sp_weight + idxA * DD);
        const float4* wB = reinterpret_cast<const float4*>(sp_weight + idxB * DD);

        float sA = 0.0f, sB = 0.0f;
        #pragma unroll
        for (int i = 0; i < DD / 128; ++i) {   // 4 iters, 8 independent LDG.128
            float4 e = s_embed[i * 32 + lane];
            float4 a = wA[i * 32 + lane];
            float4 c = wB[i * 32 + lane];
            sA = fmaf(a.x, e.x, sA); sA = fmaf(a.y, e.y, sA);
            sA = fmaf(a.z, e.z, sA); sA = fmaf(a.w, e.w, sA);
            sB = fmaf(c.x, e.x, sB); sB = fmaf(c.y, e.y, sB);
            sB = fmaf(c.z, e.z, sB); sB = fmaf(c.w, e.w, sB);
        }

        #pragma unroll
        for (int off = 16; off; off >>= 1) {
            sA += __shfl_xor_sync(0xffffffffu, sA, off);
            sB += __shfl_xor_sync(0xffffffffu, sB, off);
        }

        if (lane == 0) {
            out[b * KK + kA] = sA + __ldg(&sp_bias[idxA]);
            if (has2)
                out[b * KK + kB] = sB + __ldg(&sp_bias[idxB]);
        }
    }
}

extern "C" void kernel_launch(void* const* d_in, const int* in_sizes, int n_in,
                              void* d_out, int out_size) {
    const float* embed     = (const float*)d_in[0];
    const int*   shortlist = (const int*)  d_in[1];
    const float* sp_weight = (const float*)d_in[2];
    const float* sp_bias   = (const float*)d_in[3];
    float*       out       = (float*)d_out;

    bucket_kernel<<<BB, 256>>>(shortlist);
    dot_kernel<<<dim3(BB, NB), 256>>>(embed, sp_weight, sp_bias, out);
}

// round 5
// speedup vs baseline: 1.1473x; 1.1473x over previous
#include <cuda_runtime.h>

#define BB 512
#define KK 800
#define DD 512
#define LL 500000
#define NB 32
#define BSZ (LL / NB)          // 15625 rows per bucket, exact

// Scratch: per-b bucketed items packed as (idx << 10) | k  (idx<2^19, k<2^10)
__device__ unsigned int g_items[(size_t)BB * KK];
// Per-(b,bucket) start offsets; g_off[b][NB] = KK sentinel.
__device__ int g_off[BB * (NB + 1)];

// ---------------------------------------------------------------------------
// Kernel 1: per-b counting sort into NB idx-range buckets. 128 threads.
// ---------------------------------------------------------------------------
__global__ __launch_bounds__(128) void bucket_kernel(const int* __restrict__ shortlist)
{
    __shared__ int hist[NB];
    __shared__ int cursor[NB];
    __shared__ unsigned int s_items[KK];

    const int b = blockIdx.x;
    const int t = threadIdx.x;

    if (t < NB) hist[t] = 0;
    __syncthreads();

    for (int i = t; i < KK; i += 128) {
        unsigned idx = (unsigned)shortlist[b * KK + i];
        s_items[i] = (idx << 10) | (unsigned)i;
        atomicAdd(&hist[idx / BSZ], 1);
    }
    __syncthreads();

    if (t < 32) {
        int h = hist[t];
        int v = h;
        #pragma unroll
        for (int o = 1; o < 32; o <<= 1) {
            int n = __shfl_up_sync(0xffffffffu, v, o);
            if (t >= o) v += n;
        }
        int excl = v - h;
        cursor[t] = excl;
        g_off[b * (NB + 1) + t] = excl;
        if (t == 31) g_off[b * (NB + 1) + NB] = KK;
    }
    __syncthreads();

    for (int i = t; i < KK; i += 128) {
        unsigned it = s_items[i];
        int bucket = (int)((it >> 10) / BSZ);
        int pos = atomicAdd(&cursor[bucket], 1);
        g_items[(size_t)b * KK + pos] = it;
    }
}

// ---------------------------------------------------------------------------
// Kernel 2: dot products, grid = (b fast, bucket slow), warp per item.
// Max warp parallelism: 256 thr, 32 regs -> 8 blocks/SM (2048 threads).
// Concurrent blocks all sweep the same 2-3 idx buckets (~74 MB < L2) so
// duplicate weight rows across b hit L2; DRAM traffic == unique rows.
// ---------------------------------------------------------------------------
__global__ __launch_bounds__(256, 8) void dot_kernel(
    const float* __restrict__ embed,
    const float* __restrict__ sp_weight,
    const float* __restrict__ sp_bias,
    float*       __restrict__ out)
{
    __shared__ float4 s_embed[DD / 4];

    const int b      = blockIdx.x;
    const int bucket = blockIdx.y;

    const int begin = g_off[b * (NB + 1) + bucket];
    const int end   = g_off[b * (NB + 1) + bucket + 1];
    if (begin >= end) return;                  // empty cell: skip staging

    const float4* erow = reinterpret_cast<const float4*>(embed + (size_t)b * DD);
    for (int i = threadIdx.x; i < DD / 4; i += blockDim.x)
        s_embed[i] = erow[i];
    __syncthreads();

    const int warp = threadIdx.x >> 5;
    const int lane = threadIdx.x & 31;

    const unsigned int* items = g_items + (size_t)b * KK;

    for (int j = begin + warp; j < end; j += 8) {
        const unsigned int it  = items[j];
        const int          k   = (int)(it & 1023u);
        const long long    idx = (long long)(it >> 10);

        const float4* wrow =
            reinterpret_cast<const float4*>(sp_weight + idx * DD);

        float sum = 0.0f;
        #pragma unroll
        for (int i = 0; i < DD / 128; ++i) {   // 4 independent LDG.128
            float4 w = wrow[i * 32 + lane];
            float4 e = s_embed[i * 32 + lane];
            sum = fmaf(w.x, e.x, sum);
            sum = fmaf(w.y, e.y, sum);
            sum = fmaf(w.z, e.z, sum);
            sum = fmaf(w.w, e.w, sum);
        }

        #pragma unroll
        for (int off = 16; off; off >>= 1)
            sum += __shfl_xor_sync(0xffffffffu, sum, off);

        if (lane == 0)
            out[b * KK + k] = sum + __ldg(&sp_bias[idx]);
    }
}

extern "C" void kernel_launch(void* const* d_in, const int* in_sizes, int n_in,
                              void* d_out, int out_size) {
    const float* embed     = (const float*)d_in[0];
    const int*   shortlist = (const int*)  d_in[1];
    const float* sp_weight = (const float*)d_in[2];
    const float* sp_bias   = (const float*)d_in[3];
    float*       out       = (float*)d_out;

    bucket_kernel<<<BB, 128>>>(shortlist);
    dot_kernel<<<dim3(BB, NB), 256>>>(embed, sp_weight, sp_bias, out);
}

// round 6
// speedup vs baseline: 1.1970x; 1.0432x over previous
#include <cuda_runtime.h>

#define BB 512
#define KK 800
#define DD 512
#define LL 500000
#define NB 32
#define BSZ (LL / NB)          // 15625 rows per bucket, exact

// ---------------------------------------------------------------------------
// Single fused kernel. grid = (x=b fast, y=bucket slow), 256 threads.
//
// Each block (b, bucket):
//   1. stages embed[b,:] (2 KB) in shared
//   2. reads shortlist row b (3.2 KB, L2-resident) and compacts the items
//      whose idx lies in this bucket into a shared list (atomic push)
//   3. warp per item: float4-coalesced weight-row dot + shuffle reduction
//
// Linear bid order => all ~1184 concurrently-resident blocks work on the
// same 2-3 idx buckets => concurrent weight footprint ~74 MB < L2 126 MB
// => duplicate weight rows (across b) are L2 hits; DRAM traffic == unique
// rows (~573 MB), which is the floor for this problem at fp32.
// ---------------------------------------------------------------------------
__global__ __launch_bounds__(256, 8) void fused_kernel(
    const float* __restrict__ embed,
    const int*   __restrict__ shortlist,
    const float* __restrict__ sp_weight,
    const float* __restrict__ sp_bias,
    float*       __restrict__ out)
{
    __shared__ float4       s_embed[DD / 4];   // 2 KB
    __shared__ unsigned int s_list[KK];        // worst-case all items in bucket
    __shared__ int          s_cnt;

    const int b      = blockIdx.x;
    const int bucket = blockIdx.y;
    const int t      = threadIdx.x;

    if (t == 0) s_cnt = 0;

    // Stage embed row (L2-resident after first wave; 2 KB).
    const float4* erow = reinterpret_cast<const float4*>(embed + (size_t)b * DD);
    for (int i = t; i < DD / 4; i += 256)
        s_embed[i] = erow[i];
    __syncthreads();   // covers s_cnt init too

    // Filter + compact this bucket's items from the shortlist row.
    const int lo = bucket * BSZ;
    const int hi = lo + BSZ;
    for (int i = t; i < KK; i += 256) {
        int idx = shortlist[b * KK + i];
        if (idx >= lo && idx < hi) {
            int pos = atomicAdd(&s_cnt, 1);
            s_list[pos] = ((unsigned)idx << 10) | (unsigned)i;
        }
    }
    __syncthreads();

    const int cnt  = s_cnt;
    const int warp = t >> 5;
    const int lane = t & 31;

    for (int j = warp; j < cnt; j += 8) {
        const unsigned int it  = s_list[j];
        const int          k   = (int)(it & 1023u);
        const long long    idx = (long long)(it >> 10);

        const float4* wrow =
            reinterpret_cast<const float4*>(sp_weight + idx * DD);

        float sum = 0.0f;
        #pragma unroll
        for (int i = 0; i < DD / 128; ++i) {   // 4 independent LDG.128
            float4 w = wrow[i * 32 + lane];
            float4 e = s_embed[i * 32 + lane];
            sum = fmaf(w.x, e.x, sum);
            sum = fmaf(w.y, e.y, sum);
            sum = fmaf(w.z, e.z, sum);
            sum = fmaf(w.w, e.w, sum);
        }

        #pragma unroll
        for (int off = 16; off; off >>= 1)
            sum += __shfl_xor_sync(0xffffffffu, sum, off);

        if (lane == 0)
            out[b * KK + k] = sum + __ldg(&sp_bias[idx]);
    }
}

extern "C" void kernel_launch(void* const* d_in, const int* in_sizes, int n_in,
                              void* d_out, int out_size) {
    const float* embed     = (const float*)d_in[0];
    const int*   shortlist = (const int*)  d_in[1];
    const float* sp_weight = (const float*)d_in[2];
    const float* sp_bias   = (const float*)d_in[3];
    float*       out       = (float*)d_out;

    fused_kernel<<<dim3(BB, NB), 256>>>(embed, shortlist, sp_weight, sp_bias, out);
}

// round 7
// speedup vs baseline: 1.2188x; 1.0182x over previous
#include <cuda_runtime.h>

#define BB 512
#define KK 800
#define DD 512
#define LL 500000
#define NB 32
#define BSZ (LL / NB)          // 15625 rows per bucket, exact

// ---------------------------------------------------------------------------
// Single fused kernel. grid = (x=b fast, y=bucket slow), 256 threads.
// Per block (b,bucket): stage embed[b] in shared + filter this bucket's items
// out of shortlist row b (one int4 per thread, warp-aggregated compaction),
// ONE barrier, then warp-per-item float4 dot products.
//
// Linear bid order => concurrent blocks share a ~74 MB weight window < L2,
// so duplicate rows across b are L2 hits; DRAM traffic == unique rows.
// ---------------------------------------------------------------------------
__global__ __launch_bounds__(256, 8) void fused_kernel(
    const float* __restrict__ embed,
    const int*   __restrict__ shortlist,
    const float* __restrict__ sp_weight,
    const float* __restrict__ sp_bias,
    float*       __restrict__ out)
{
    __shared__ float4       s_embed[DD / 4];   // 2 KB
    __shared__ unsigned int s_list[KK];
    __shared__ int          s_cnt;

    const int b      = blockIdx.x;
    const int bucket = blockIdx.y;
    const int t      = threadIdx.x;
    const int lane   = t & 31;

    if (t == 0) s_cnt = 0;
    // cheap barrier-free init is unsafe; fold init visibility into the
    // ballot/atomic phase by syncing once before pushes:
    __syncthreads();

    // ---- overlapped prologue: embed staging + shortlist filter ----
    const float4* erow = reinterpret_cast<const float4*>(embed + (size_t)b * DD);
    if (t < DD / 4)                    // 128 threads, 1 float4 each
        s_embed[t] = erow[t];

    const int lo = bucket * BSZ;
    const int hi = lo + BSZ;

    const int4* srow = reinterpret_cast<const int4*>(shortlist + (size_t)b * KK);
    int4 v = make_int4(-1, -1, -1, -1);
    if (t < KK / 4)                    // 200 threads, 1 int4 each
        v = srow[t];

    // warp-aggregated compaction, component by component
    #pragma unroll
    for (int c = 0; c < 4; ++c) {
        int idx = (c == 0) ? v.x : (c == 1) ? v.y : (c == 2) ? v.z : v.w;
        bool m = (t < KK / 4) && (idx >= lo) && (idx < hi);
        unsigned bal = __ballot_sync(0xffffffffu, m);
        if (bal) {
            int base = 0;
            if (lane == 0) base = atomicAdd(&s_cnt, __popc(bal));
            base = __shfl_sync(0xffffffffu, base, 0);
            if (m) {
                int off = __popc(bal & ((1u << lane) - 1u));
                int k = t * 4 + c;
                s_list[base + off] = ((unsigned)idx << 10) | (unsigned)k;
            }
        }
    }
    __syncthreads();

    // ---- main: warp per item, float4-coalesced weight-row dot ----
    const int cnt  = s_cnt;
    const int warp = t >> 5;

    for (int j = warp; j < cnt; j += 8) {
        const unsigned int it  = s_list[j];
        const int          k   = (int)(it & 1023u);
        const long long    idx = (long long)(it >> 10);

        const float4* wrow =
            reinterpret_cast<const float4*>(sp_weight + idx * DD);

        float sum = 0.0f;
        #pragma unroll
        for (int i = 0; i < DD / 128; ++i) {   // 4 independent LDG.128
            float4 w = wrow[i * 32 + lane];
            float4 e = s_embed[i * 32 + lane];
            sum = fmaf(w.x, e.x, sum);
            sum = fmaf(w.y, e.y, sum);
            sum = fmaf(w.z, e.z, sum);
            sum = fmaf(w.w, e.w, sum);
        }

        #pragma unroll
        for (int off = 16; off; off >>= 1)
            sum += __shfl_xor_sync(0xffffffffu, sum, off);

        if (lane == 0)
            out[b * KK + k] = sum + __ldg(&sp_bias[idx]);
    }
}

extern "C" void kernel_launch(void* const* d_in, const int* in_sizes, int n_in,
                              void* d_out, int out_size) {
    const float* embed     = (const float*)d_in[0];
    const int*   shortlist = (const int*)  d_in[1];
    const float* sp_weight = (const float*)d_in[2];
    const float* sp_bias   = (const float*)d_in[3];
    float*       out       = (float*)d_out;

    fused_kernel<<<dim3(BB, NB), 256>>>(embed, shortlist, sp_weight, sp_bias, out);
}

// round 8
// speedup vs baseline: 1.2234x; 1.0038x over previous
#include <cuda_runtime.h>

#define BB 512
#define KK 800
#define DD 512
#define LL 500000
#define NB 24
#define BSZ ((LL + NB - 1) / NB)   // 20834; last bucket slightly smaller

// ---------------------------------------------------------------------------
// Single fused kernel. grid = (x=b fast, y=bucket slow), 256 threads.
// Per block (b,bucket): stage embed[b] in shared + filter this bucket's items
// out of shortlist row b (one int4 per thread, warp-aggregated compaction),
// ONE barrier, then warp-per-item float4 dot products.
//
// Linear bid order => the ~1184 concurrently-resident blocks span ~2.3
// buckets => concurrent weight footprint ~96 MB < 126 MB L2, so duplicate
// weight rows across b are L2 hits; DRAM traffic == unique rows (~573 MB).
// ---------------------------------------------------------------------------
__global__ __launch_bounds__(256, 8) void fused_kernel(
    const float* __restrict__ embed,
    const int*   __restrict__ shortlist,
    const float* __restrict__ sp_weight,
    const float* __restrict__ sp_bias,
    float*       __restrict__ out)
{
    __shared__ float4       s_embed[DD / 4];   // 2 KB
    __shared__ unsigned int s_list[KK];
    __shared__ int          s_cnt;

    const int b      = blockIdx.x;
    const int bucket = blockIdx.y;
    const int t      = threadIdx.x;
    const int lane   = t & 31;

    if (t == 0) s_cnt = 0;
    __syncthreads();

    // ---- overlapped prologue: embed staging + shortlist filter ----
    const float4* erow = reinterpret_cast<const float4*>(embed + (size_t)b * DD);
    if (t < DD / 4)                    // 128 threads, 1 float4 each
        s_embed[t] = erow[t];

    const int lo = bucket * BSZ;
    const int hi = lo + BSZ;           // last bucket: hi > LL harmless (idx < LL)

    const int4* srow = reinterpret_cast<const int4*>(shortlist + (size_t)b * KK);
    int4 v = make_int4(-1, -1, -1, -1);
    if (t < KK / 4)                    // 200 threads, 1 int4 each
        v = srow[t];

    // warp-aggregated compaction, component by component
    #pragma unroll
    for (int c = 0; c < 4; ++c) {
        int idx = (c == 0) ? v.x : (c == 1) ? v.y : (c == 2) ? v.z : v.w;
        bool m = (t < KK / 4) && (idx >= lo) && (idx < hi);
        unsigned bal = __ballot_sync(0xffffffffu, m);
        if (bal) {
            int base = 0;
            if (lane == 0) base = atomicAdd(&s_cnt, __popc(bal));
            base = __shfl_sync(0xffffffffu, base, 0);
            if (m) {
                int off = __popc(bal & ((1u << lane) - 1u));
                int k = t * 4 + c;
                s_list[base + off] = ((unsigned)idx << 10) | (unsigned)k;
            }
        }
    }
    __syncthreads();

    // ---- main: warp per item, float4-coalesced weight-row dot ----
    const int cnt  = s_cnt;
    const int warp = t >> 5;

    for (int j = warp; j < cnt; j += 8) {
        const unsigned int it  = s_list[j];
        const int          k   = (int)(it & 1023u);
        const long long    idx = (long long)(it >> 10);

        const float4* wrow =
            reinterpret_cast<const float4*>(sp_weight + idx * DD);

        float sum = 0.0f;
        #pragma unroll
        for (int i = 0; i < DD / 128; ++i) {   // 4 independent LDG.128
            float4 w = wrow[i * 32 + lane];
            float4 e = s_embed[i * 32 + lane];
            sum = fmaf(w.x, e.x, sum);
            sum = fmaf(w.y, e.y, sum);
            sum = fmaf(w.z, e.z, sum);
            sum = fmaf(w.w, e.w, sum);
        }

        #pragma unroll
        for (int off = 16; off; off >>= 1)
            sum += __shfl_xor_sync(0xffffffffu, sum, off);

        if (lane == 0)
            out[b * KK + k] = sum + __ldg(&sp_bias[idx]);
    }
}

extern "C" void kernel_launch(void* const* d_in, const int* in_sizes, int n_in,
                              void* d_out, int out_size) {
    const float* embed     = (const float*)d_in[0];
    const int*   shortlist = (const int*)  d_in[1];
    const float* sp_weight = (const float*)d_in[2];
    const float* sp_bias   = (const float*)d_in[3];
    float*       out       = (float*)d_out;

    fused_kernel<<<dim3(BB, NB), 256>>>(embed, shortlist, sp_weight, sp_bias, out);
}